// round 15
// baseline (speedup 1.0000x reference)
#include <cuda_runtime.h>

// out[b,e] = sparsity[b,e] * sum_h hs[b,h] * ws[e,h]
//   hs[b,h] = sum_m hidden[b,m,h]   (4 MB)  -> kernel 1 (tiny, transposed scratch)
//   ws[e,h] = sum_n weight[e,h,n]   (32 MB) -> kernel 2 = R5 streamer +
//             WARP-AUTONOMOUS epilogue: no barrier, no smem, 1 RED/lane.
// A=1, B=32, M=32, H=1024, E=8, N=1024.

#define Bn 32
#define Mn 32
#define Hn 1024
#define En 8
#define Nn 1024

__device__ float g_hsT[Hn * Bn];   // hsT[h*32 + b]  (128 KB, L2-resident)
__device__ float g_spT[En * Bn];   // spT[e*32 + b]  (1 KB)

// ---- Kernel 1: hidden reduction (coalesced reads), transposed outputs ----
// 256 blocks x 128 threads. b = bid>>3, h = (bid&7)*128 + tid.
__global__ void __launch_bounds__(128) hidden_kernel(
    const float* __restrict__ hidden,
    const float* __restrict__ sparsity,
    float* __restrict__ out)
{
    const int bid = blockIdx.x;
    const int b   = bid >> 3;
    const int h   = ((bid & 7) << 7) + threadIdx.x;
    const float* base = hidden + (size_t)b * Mn * Hn + h;

    float s = 0.f;
    #pragma unroll
    for (int m = 0; m < Mn; m++)
        s += base[m * Hn];
    g_hsT[h * Bn + b] = s;

    if (bid < 2) out[bid * 128 + threadIdx.x] = 0.f;    // zero 256 outputs
    if (bid == 0) {
        // transposed sparsity: 128 threads cover 256 entries (2 each)
        #pragma unroll
        for (int j = 0; j < 2; j++) {
            const int idx = threadIdx.x + j * 128;      // [0,256)
            const int e   = idx >> 5;
            const int bb  = idx & 31;
            g_spT[e * Bn + bb] = sparsity[bb * En + e];
        }
    }
}

// ---- Kernel 2: R5 weight streamer + warp-autonomous dot epilogue ----
// 512 blocks x 256 threads; warp w owns rows r0 = bid*16 + 2w, r0+1.
// NO __syncthreads, NO smem: each warp finishes and REDs independently.
__global__ void __launch_bounds__(256) weight_kernel(
    const float* __restrict__ weight,
    float* __restrict__ out)
{
    const int tid  = threadIdx.x;
    const int lane = tid & 31;
    const int wid  = tid >> 5;
    const int r0   = blockIdx.x * 16 + wid * 2;

    const float4* rowA = reinterpret_cast<const float4*>(weight + (size_t)r0 * Nn);
    const float4* rowB = reinterpret_cast<const float4*>(weight + (size_t)(r0 + 1) * Nn);

    float s0 = 0.f, s1 = 0.f;
    #pragma unroll
    for (int k = 0; k < Nn / 4 / 32; k++) {   // 8 batches of 2 indep LDG.128
        float4 a = rowA[lane + k * 32];
        float4 b = rowB[lane + k * 32];
        s0 += (a.x + a.y) + (a.z + a.w);
        s1 += (b.x + b.y) + (b.z + b.w);
    }
    #pragma unroll
    for (int off = 16; off > 0; off >>= 1) {
        s0 += __shfl_xor_sync(0xffffffffu, s0, off);
        s1 += __shfl_xor_sync(0xffffffffu, s1, off);
    }
    // all lanes now hold ws[e,h0] (=s0) and ws[e,h0+1] (=s1)

    const int e  = r0 >> 10;
    const int h0 = r0 & (Hn - 1);

    // coalesced epilogue: lane = b; 3 single-line warp loads + 1 RED per lane
    const float hs0 = g_hsT[h0 * Bn + lane];
    const float hs1 = g_hsT[(h0 + 1) * Bn + lane];
    const float sp  = g_spT[e * Bn + lane];
    const float p   = (s0 * hs0 + s1 * hs1) * sp;

    atomicAdd(&out[lane * En + e], p);        // 131K lane-ops / 256 addrs
}

extern "C" void kernel_launch(void* const* d_in, const int* in_sizes, int n_in,
                              void* d_out, int out_size)
{
    const float* hidden   = (const float*)d_in[0];
    const float* sparsity = (const float*)d_in[1];
    const float* weight   = (const float*)d_in[2];
    float* out = (float*)d_out;

    hidden_kernel<<<256, 128>>>(hidden, sparsity, out);
    weight_kernel<<<(En * Hn) / 16, 256>>>(weight, out);   // 512 blocks
}

// round 16
// speedup vs baseline: 3.6192x; 3.6192x over previous
#include <cuda_runtime.h>

// out[b,e] = sparsity[b,e] * sum_h hs[b,h] * ws[e,h]
//   ws[e,h] = sum_n weight[e,h,n]  (32 MB) -> kernel 1: R5 pure streamer (PROTECTED)
//   dot is linear in m -> kernel 2: block=(b, 4-m group), partial dots, 8 REDs/block.
// Atomic budget law: keep total atomic lane-ops ~2K (0.3us/1K op cost).
// A=1, B=32, M=32, H=1024, E=8, N=1024.

#define Bn 32
#define Mn 32
#define Hn 1024
#define En 8
#define Nn 1024

__device__ float g_wsT[Hn * En];   // wsT[h*8 + e]  (32 KB, L2-resident)

// ---- Kernel 1: R5 pure weight streamer (verbatim; ~5.5us). Zeroes out. ----
__global__ void __launch_bounds__(256) weight_kernel(
    const float* __restrict__ weight,
    float* __restrict__ out)
{
    const int tid  = threadIdx.x;
    const int lane = tid & 31;
    const int wid  = tid >> 5;
    const int r0   = blockIdx.x * 16 + wid * 2;

    const float4* rowA = reinterpret_cast<const float4*>(weight + (size_t)r0 * Nn);
    const float4* rowB = reinterpret_cast<const float4*>(weight + (size_t)(r0 + 1) * Nn);

    float s0 = 0.f, s1 = 0.f;
    #pragma unroll
    for (int k = 0; k < Nn / 4 / 32; k++) {
        float4 a = rowA[lane + k * 32];
        float4 b = rowB[lane + k * 32];
        s0 += (a.x + a.y) + (a.z + a.w);
        s1 += (b.x + b.y) + (b.z + b.w);
    }
    #pragma unroll
    for (int off = 16; off > 0; off >>= 1) {
        s0 += __shfl_xor_sync(0xffffffffu, s0, off);
        s1 += __shfl_xor_sync(0xffffffffu, s1, off);
    }
    if (lane == 0) {
        const int e  = r0 >> 10;
        const int h0 = r0 & (Hn - 1);
        g_wsT[h0 * En + e]       = s0;
        g_wsT[(h0 + 1) * En + e] = s1;
    }
    if (blockIdx.x == 0) out[tid] = 0.f;   // zero all 256 outputs
}

// ---- Kernel 2: partial-m dot. 256 blocks x 256 threads (~14 warps/SM). ----
// Block (b = bid>>3, mq = bid&7): m in [mq*4, mq*4+4), ALL h.
// Thread tid owns float4 h-column tid: 4 contiguous independent LDG.128
// (warp = 512B contiguous per load). Dots partial hs against coalesced wsT.
// Block reduce -> 8 REDs (2048 lane-ops total).
__global__ void __launch_bounds__(256) hidden_dot_kernel(
    const float* __restrict__ hidden,
    const float* __restrict__ sparsity,
    float* __restrict__ out)
{
    const int bid  = blockIdx.x;
    const int tid  = threadIdx.x;
    const int lane = tid & 31;
    const int wid  = tid >> 5;
    const int b    = bid >> 3;
    const int mq   = bid & 7;

    const float4* H4 = reinterpret_cast<const float4*>(
        hidden + (size_t)(b * Mn + mq * 4) * Hn);

    // 4 independent contiguous LDG.128
    float4 v0 = H4[tid];
    float4 v1 = H4[tid + 256];
    float4 v2 = H4[tid + 512];
    float4 v3 = H4[tid + 768];
    float4 hs4 = make_float4((v0.x + v1.x) + (v2.x + v3.x),
                             (v0.y + v1.y) + (v2.y + v3.y),
                             (v0.z + v1.z) + (v2.z + v3.z),
                             (v0.w + v1.w) + (v2.w + v3.w));

    // wsT for h = tid*4 .. tid*4+3: 32 consecutive floats = 8 float4 (coalesced)
    const float4* wt = reinterpret_cast<const float4*>(g_wsT) + tid * 8;
    float p[8];
    {
        float4 w0 = wt[0], w1 = wt[1];   // h0: e0..3, e4..7
        p[0] = hs4.x * w0.x; p[1] = hs4.x * w0.y; p[2] = hs4.x * w0.z; p[3] = hs4.x * w0.w;
        p[4] = hs4.x * w1.x; p[5] = hs4.x * w1.y; p[6] = hs4.x * w1.z; p[7] = hs4.x * w1.w;
        float4 w2 = wt[2], w3 = wt[3];   // h1
        p[0] += hs4.y * w2.x; p[1] += hs4.y * w2.y; p[2] += hs4.y * w2.z; p[3] += hs4.y * w2.w;
        p[4] += hs4.y * w3.x; p[5] += hs4.y * w3.y; p[6] += hs4.y * w3.z; p[7] += hs4.y * w3.w;
        float4 w4 = wt[4], w5 = wt[5];   // h2
        p[0] += hs4.z * w4.x; p[1] += hs4.z * w4.y; p[2] += hs4.z * w4.z; p[3] += hs4.z * w4.w;
        p[4] += hs4.z * w5.x; p[5] += hs4.z * w5.y; p[6] += hs4.z * w5.z; p[7] += hs4.z * w5.w;
        float4 w6 = wt[6], w7 = wt[7];   // h3
        p[0] += hs4.w * w6.x; p[1] += hs4.w * w6.y; p[2] += hs4.w * w6.z; p[3] += hs4.w * w6.w;
        p[4] += hs4.w * w7.x; p[5] += hs4.w * w7.y; p[6] += hs4.w * w7.z; p[7] += hs4.w * w7.w;
    }

    #pragma unroll
    for (int off = 16; off > 0; off >>= 1)
        #pragma unroll
        for (int e = 0; e < 8; e++)
            p[e] += __shfl_xor_sync(0xffffffffu, p[e], off);

    __shared__ float sm[8][8];          // [warp][e]
    if (lane == 0)
        #pragma unroll
        for (int e = 0; e < 8; e++) sm[wid][e] = p[e];
    __syncthreads();

    if (tid < En) {
        float v = 0.f;
        #pragma unroll
        for (int w = 0; w < 8; w++) v += sm[w][tid];
        const int idx = b * En + tid;
        atomicAdd(&out[idx], v * sparsity[idx]);   // 8 REDs/block, 2048 total
    }
}

extern "C" void kernel_launch(void* const* d_in, const int* in_sizes, int n_in,
                              void* d_out, int out_size)
{
    const float* hidden   = (const float*)d_in[0];
    const float* sparsity = (const float*)d_in[1];
    const float* weight   = (const float*)d_in[2];
    float* out = (float*)d_out;

    weight_kernel<<<(En * Hn) / 16, 256>>>(weight, out);           // 512 blocks
    hidden_dot_kernel<<<Bn * 8, 256>>>(hidden, sparsity, out);     // 256 blocks
}

// round 17
// speedup vs baseline: 4.3839x; 1.2113x over previous
#include <cuda_runtime.h>

// out[b,e] = sparsity[b,e] * sum_h hs[b,h] * ws[e,h]
//   ws[e,h] = sum_n weight[e,h,n]  (32 MB) -> kernel 1: R5 pure streamer (PROTECTED)
//   kernel 2: block=(b, 4-m group); wsE staged to smem COALESCED, conflict-free LDS.
// Atomic budget law: total RED lane-ops ~2K. L1 law: no >=128B per-thread strides.
// A=1, B=32, M=32, H=1024, E=8, N=1024.

#define Bn 32
#define Mn 32
#define Hn 1024
#define En 8
#define Nn 1024

__device__ float g_wsE[En * Hn];   // wsE[e*1024 + h]  (32 KB, L2-resident)

// ---- Kernel 1: R5 pure weight streamer (verbatim loop; ~5.5us). Zeroes out. ----
__global__ void __launch_bounds__(256) weight_kernel(
    const float* __restrict__ weight,
    float* __restrict__ out)
{
    const int tid  = threadIdx.x;
    const int lane = tid & 31;
    const int wid  = tid >> 5;
    const int r0   = blockIdx.x * 16 + wid * 2;

    const float4* rowA = reinterpret_cast<const float4*>(weight + (size_t)r0 * Nn);
    const float4* rowB = reinterpret_cast<const float4*>(weight + (size_t)(r0 + 1) * Nn);

    float s0 = 0.f, s1 = 0.f;
    #pragma unroll
    for (int k = 0; k < Nn / 4 / 32; k++) {
        float4 a = rowA[lane + k * 32];
        float4 b = rowB[lane + k * 32];
        s0 += (a.x + a.y) + (a.z + a.w);
        s1 += (b.x + b.y) + (b.z + b.w);
    }
    #pragma unroll
    for (int off = 16; off > 0; off >>= 1) {
        s0 += __shfl_xor_sync(0xffffffffu, s0, off);
        s1 += __shfl_xor_sync(0xffffffffu, s1, off);
    }
    if (lane == 0) {
        // r0 = e*1024 + h0  ->  e-major scratch (row r0 maps directly)
        g_wsE[r0]     = s0;
        g_wsE[r0 + 1] = s1;
    }
    if (blockIdx.x == 0) out[tid] = 0.f;   // zero all 256 outputs
}

// ---- Kernel 2: partial-m dot with smem-staged wsE. 256 blocks x 256 threads. ----
// Block (b = bid>>3, mq = bid&7): m in [mq*4, mq*4+4), ALL h.
// Stage: 32 KB wsE -> smem, coalesced float4 (thread t loads wsE4[e*256+t]).
// Dot:   thread t owns h = 4t..4t+3; reads sm_ws4[e][t] (conflict-free LDS.128).
// Reduce + 8 REDs/block (2048 lane-ops total).
__global__ void __launch_bounds__(256) hidden_dot_kernel(
    const float* __restrict__ hidden,
    const float* __restrict__ sparsity,
    float* __restrict__ out)
{
    const int bid  = blockIdx.x;
    const int tid  = threadIdx.x;
    const int lane = tid & 31;
    const int wid  = tid >> 5;
    const int b    = bid >> 3;
    const int mq   = bid & 7;

    __shared__ float4 sm_ws4[En][Hn / 4];   // [e][h4]  32 KB
    __shared__ float  sm_red[8][8];         // [warp][e]

    // ---- Stage wsE into smem (coalesced reads, conflict-free writes) ----
    {
        const float4* W4 = reinterpret_cast<const float4*>(g_wsE);
        #pragma unroll
        for (int e = 0; e < En; e++)
            sm_ws4[e][tid] = W4[e * (Hn / 4) + tid];
    }

    // ---- Hidden: 4 contiguous independent LDG.128 (issued before barrier) ----
    const float4* H4 = reinterpret_cast<const float4*>(
        hidden + (size_t)(b * Mn + mq * 4) * Hn);
    float4 v0 = H4[tid];
    float4 v1 = H4[tid + 256];
    float4 v2 = H4[tid + 512];
    float4 v3 = H4[tid + 768];
    float4 hs4 = make_float4((v0.x + v1.x) + (v2.x + v3.x),
                             (v0.y + v1.y) + (v2.y + v3.y),
                             (v0.z + v1.z) + (v2.z + v3.z),
                             (v0.w + v1.w) + (v2.w + v3.w));

    __syncthreads();   // wsE staged

    // ---- Dot: thread t, h = 4t..4t+3 vs 8 experts (8 conflict-free LDS.128) ----
    float p[8];
    #pragma unroll
    for (int e = 0; e < En; e++) {
        float4 w = sm_ws4[e][tid];
        p[e] = hs4.x * w.x + hs4.y * w.y + hs4.z * w.z + hs4.w * w.w;
    }

    #pragma unroll
    for (int off = 16; off > 0; off >>= 1)
        #pragma unroll
        for (int e = 0; e < 8; e++)
            p[e] += __shfl_xor_sync(0xffffffffu, p[e], off);

    if (lane == 0)
        #pragma unroll
        for (int e = 0; e < 8; e++) sm_red[wid][e] = p[e];
    __syncthreads();

    if (tid < En) {
        float v = 0.f;
        #pragma unroll
        for (int w = 0; w < 8; w++) v += sm_red[w][tid];
        const int idx = b * En + tid;
        atomicAdd(&out[idx], v * sparsity[idx]);   // 8 REDs/block
    }
}

extern "C" void kernel_launch(void* const* d_in, const int* in_sizes, int n_in,
                              void* d_out, int out_size)
{
    const float* hidden   = (const float*)d_in[0];
    const float* sparsity = (const float*)d_in[1];
    const float* weight   = (const float*)d_in[2];
    float* out = (float*)d_out;

    weight_kernel<<<(En * Hn) / 16, 256>>>(weight, out);           // 512 blocks
    hidden_dot_kernel<<<Bn * 8, 256>>>(hidden, sparsity, out);     // 256 blocks
}